// round 5
// baseline (speedup 1.0000x reference)
#include <cuda_runtime.h>
#include <cstdint>

// Problem: 2x2 sum-of-squares pooling + sqrt.
// Input  per batch: x[i*512 + j*16 + c], i,j in [0,32), c in [0,16)  (16384 f32)
// Output per batch: y[oi*256 + oj*16 + c], oi,oj in [0,16)           (4096  f32)
// y = sqrt( sum_{di,dj in {0,1}} x[2oi+di, 2oj+dj, c]^2 )

#define BATCH     1024
#define IN_PER_B  16384
#define OUT_PER_B 4096
#define TOTAL_V4  (BATCH * OUT_PER_B / 4)   // 1,048,576 float4 outputs
#define NBLOCKS   1024
#define NTHREADS  256
#define ITERS     4                          // TOTAL_V4 / (NBLOCKS*NTHREADS)
#define STRIDE_V4 (NBLOCKS * NTHREADS)       // 262,144

__device__ __forceinline__ float fsqrt_approx(float v) {
    float r;
    asm("sqrt.approx.f32 %0, %1;" : "=f"(r) : "f"(v));
    return r;
}

// Streaming store: output is write-once, never re-read.
__device__ __forceinline__ void st_cs4(float4* p, float4 v) {
    asm volatile("st.global.cs.v4.f32 [%0], {%1,%2,%3,%4};"
                 :: "l"(p), "f"(v.x), "f"(v.y), "f"(v.z), "f"(v.w)
                 : "memory");
}

__global__ __launch_bounds__(NTHREADS)
void pool3d_kernel(const float* __restrict__ x, float* __restrict__ out) {
    int tid = blockIdx.x * NTHREADS + threadIdx.x;   // [0, STRIDE_V4)
    const float4* __restrict__ xin4 = reinterpret_cast<const float4*>(x);
    float4* __restrict__ out4 = reinterpret_cast<float4*>(out);

    // Batch the loads for all ITERS iterations first (high MLP), then compute+store.
    float4 a0[ITERS], a1[ITERS], a2[ITERS], a3[ITERS];
    int base_in[ITERS];

#pragma unroll
    for (int it = 0; it < ITERS; it++) {
        int idx = tid + it * STRIDE_V4;
        // idx = b*1024 + oi*64 + oj*4 + c4
        int b  = idx >> 10;
        int r  = idx & 1023;
        int oi = r >> 6;
        int rr = r & 63;
        int oj = rr >> 2;
        int c4 = rr & 3;
        // input float4 offset: b*4096 + 256*oi + 8*oj + c4
        int base = (b << 12) + (oi << 8) + (oj << 3) + c4;
        base_in[it] = base;
        a0[it] = xin4[base];          // (2oi,   2oj)
        a1[it] = xin4[base + 4];      // (2oi,   2oj+1)
        a2[it] = xin4[base + 128];    // (2oi+1, 2oj)
        a3[it] = xin4[base + 132];    // (2oi+1, 2oj+1)
    }

#pragma unroll
    for (int it = 0; it < ITERS; it++) {
        float4 y;
        y.x = fsqrt_approx(a0[it].x*a0[it].x + a1[it].x*a1[it].x + a2[it].x*a2[it].x + a3[it].x*a3[it].x);
        y.y = fsqrt_approx(a0[it].y*a0[it].y + a1[it].y*a1[it].y + a2[it].y*a2[it].y + a3[it].y*a3[it].y);
        y.z = fsqrt_approx(a0[it].z*a0[it].z + a1[it].z*a1[it].z + a2[it].z*a2[it].z + a3[it].z*a3[it].z);
        y.w = fsqrt_approx(a0[it].w*a0[it].w + a1[it].w*a1[it].w + a2[it].w*a2[it].w + a3[it].w*a3[it].w);
        st_cs4(out4 + tid + it * STRIDE_V4, y);
    }
}

extern "C" void kernel_launch(void* const* d_in, const int* in_sizes, int n_in,
                              void* d_out, int out_size) {
    const float* x = (const float*)d_in[0];   // input_state [1024, 16384]
    // d_in[1] is T — structural 0/1 pooling matrix, not needed at runtime.
    float* out = (float*)d_out;               // [1024, 4096]

    pool3d_kernel<<<NBLOCKS, NTHREADS>>>(x, out);
}

// round 6
// speedup vs baseline: 1.1851x; 1.1851x over previous
#include <cuda_runtime.h>
#include <cstdint>

// Problem: 2x2 sum-of-squares pooling + sqrt.
// Input  per batch: x[i*512 + j*16 + c], i,j in [0,32), c in [0,16)  (16384 f32)
// Output per batch: y[oi*256 + oj*16 + c], oi,oj in [0,16)           (4096  f32)
// y = sqrt( sum_{di,dj in {0,1}} x[2oi+di, 2oj+dj, c]^2 )

#define BATCH     1024
#define IN_PER_B  16384
#define OUT_PER_B 4096
#define TOTAL_V4  (BATCH * OUT_PER_B / 4)   // 1,048,576 float4 outputs
#define NBLOCKS   2048
#define NTHREADS  256
#define STRIDE_V4 (NBLOCKS * NTHREADS)      // 524,288 -> exactly 2 iterations/thread

__device__ __forceinline__ float fsqrt_approx(float v) {
    float r;
    asm("sqrt.approx.f32 %0, %1;" : "=f"(r) : "f"(v));
    return r;
}

// Streaming store: output is write-once, never re-read.
__device__ __forceinline__ void st_cs4(float4* p, float4 v) {
    asm volatile("st.global.cs.v4.f32 [%0], {%1,%2,%3,%4};"
                 :: "l"(p), "f"(v.x), "f"(v.y), "f"(v.z), "f"(v.w)
                 : "memory");
}

__global__ __launch_bounds__(NTHREADS)
void pool3d_kernel(const float* __restrict__ x, float* __restrict__ out) {
    int tid = blockIdx.x * NTHREADS + threadIdx.x;   // [0, STRIDE_V4)
    const float4* __restrict__ xin4 = reinterpret_cast<const float4*>(x);
    float4* __restrict__ out4 = reinterpret_cast<float4*>(out);

#pragma unroll
    for (int it = 0; it < 2; it++) {
        int idx = tid + it * STRIDE_V4;
        // idx = b*1024 + oi*64 + oj*4 + c4
        int b  = idx >> 10;
        int r  = idx & 1023;
        int oi = r >> 6;
        int rr = r & 63;
        int oj = rr >> 2;
        int c4 = rr & 3;
        // input float4 offset: b*4096 + 256*oi + 8*oj + c4
        int base = (b << 12) + (oi << 8) + (oj << 3) + c4;

        float4 a0 = xin4[base];          // (2oi,   2oj)
        float4 a1 = xin4[base + 4];      // (2oi,   2oj+1)
        float4 a2 = xin4[base + 128];    // (2oi+1, 2oj)
        float4 a3 = xin4[base + 132];    // (2oi+1, 2oj+1)

        float4 y;
        y.x = fsqrt_approx(a0.x*a0.x + a1.x*a1.x + a2.x*a2.x + a3.x*a3.x);
        y.y = fsqrt_approx(a0.y*a0.y + a1.y*a1.y + a2.y*a2.y + a3.y*a3.y);
        y.z = fsqrt_approx(a0.z*a0.z + a1.z*a1.z + a2.z*a2.z + a3.z*a3.z);
        y.w = fsqrt_approx(a0.w*a0.w + a1.w*a1.w + a2.w*a2.w + a3.w*a3.w);

        st_cs4(out4 + idx, y);
    }
}

extern "C" void kernel_launch(void* const* d_in, const int* in_sizes, int n_in,
                              void* d_out, int out_size) {
    const float* x = (const float*)d_in[0];   // input_state [1024, 16384]
    // d_in[1] is T — structural 0/1 pooling matrix, not needed at runtime.
    float* out = (float*)d_out;               // [1024, 4096]

    pool3d_kernel<<<NBLOCKS, NTHREADS>>>(x, out);
}